// round 4
// baseline (speedup 1.0000x reference)
#include <cuda_runtime.h>

#define BB 8
#define NN 9216
#define FF 1024
#define KK 4096
#define NBLK 72   // 9 * 8 blocks, all co-resident on 148 SMs

// Scratch (device globals; zero at module load; every call restores invariants)
__device__ int  g_hist[BB * KK];    // per-batch voxel histogram (zero on entry)
__device__ int  g_off[BB * KK];     // scatter cursor per voxel
__device__ int2 g_slotSC[BB * KK];  // per output slot (rank): {start, count}
__device__ int  g_sorted[BB * NN];  // point indices grouped by voxel
__device__ int  g_count[BB];        // occupied voxels per batch
__device__ unsigned g_arrive[2];    // grid barrier arrive counters
__device__ unsigned g_depart[2];    // grid barrier depart counters

// Self-resetting grid barrier: safe because all NBLK blocks are co-resident.
__device__ __forceinline__ void grid_sync(int s) {
    __syncthreads();
    if (threadIdx.x == 0) {
        __threadfence();
        atomicAdd(&g_arrive[s], 1u);
        while (*((volatile unsigned*)&g_arrive[s]) < NBLK) {}
        __threadfence();
        unsigned d = atomicAdd(&g_depart[s], 1u);
        if (d == NBLK - 1) {  // everyone has passed the spin; safe to reset
            g_arrive[s] = 0;
            __threadfence();
            g_depart[s] = 0;
        }
    }
    __syncthreads();
}

// Compact voxel id: cx*256+cy*16+cz preserves the reference HASH_M=1024
// lexicographic ordering; the per-batch min subtraction is a constant per-axis
// shift and changes neither grouping nor order, hence ranks are unchanged.
__device__ __forceinline__ int voxel_id(const float* __restrict__ bx, int i) {
    float x = bx[i * 3 + 0];
    float y = bx[i * 3 + 1];
    float z = bx[i * 3 + 2];
    int cx = (int)floorf(__fdiv_rn(x, 0.2f));
    int cy = (int)floorf(__fdiv_rn(y, 0.2f));
    int cz = (int)floorf(__fdiv_rn(z, 0.2f));
    cx = min(max(cx, 0), 15);
    cy = min(max(cy, 0), 15);
    cz = min(max(cz, 0), 15);
    return (cx << 8) | (cy << 4) | cz;
}

// Fused build: histogram -> per-batch dual scan -> counting-sort scatter.
// grid (9, BB) x 256; each thread owns 4 points (ids stay in registers).
__global__ __launch_bounds__(256) void build_kernel(const float* __restrict__ xyz,
                                                    float* __restrict__ out_tail) {
    const int b = blockIdx.y;
    const int tid = threadIdx.x;
    const float* bx = xyz + (size_t)b * NN * 3;

    // ---- Phase 1: voxelize + histogram (ids kept in registers) ----
    int vid[4], pid[4];
#pragma unroll
    for (int j = 0; j < 4; j++) {
        int i = blockIdx.x * 1024 + tid + j * 256;  // 9*1024 == NN exactly
        pid[j] = i;
        vid[j] = voxel_id(bx, i);
        atomicAdd(&g_hist[b * KK + vid[j]], 1);
    }

    grid_sync(0);

    // ---- Phase 2: per-batch packed dual exclusive scan (8 scan blocks) ----
    // low 16 bits: point-count prefix (<=9216<2^16); high bits: occupancy
    // prefix == compacted rank.
    if (blockIdx.x == 0) {
        __shared__ int wsum[8];
        __shared__ int s_tot;

        // zero the slot table (empty ranks must yield zero output rows)
        {
            int2 z = make_int2(0, 0);
#pragma unroll
            for (int j = 0; j < 16; j++) g_slotSC[b * KK + tid * 16 + j] = z;
        }
        __syncthreads();

        const int base = tid * 16;
        int cnts[16], e[16];
        int ts = 0;
#pragma unroll
        for (int j = 0; j < 16; j++) {
            int c = g_hist[b * KK + base + j];
            cnts[j] = c;
            e[j] = c | ((c > 0) << 16);
            ts += e[j];
        }

        const int lane = tid & 31;
        const int wid = tid >> 5;

        int incl = ts;
#pragma unroll
        for (int off = 1; off < 32; off <<= 1) {
            int n = __shfl_up_sync(0xffffffffu, incl, off);
            if (lane >= off) incl += n;
        }
        if (lane == 31) wsum[wid] = incl;
        __syncthreads();

        if (wid == 0 && lane < 8) {
            int wv = wsum[lane];
            int wi = wv;
#pragma unroll
            for (int off = 1; off < 8; off <<= 1) {
                int n = __shfl_up_sync(0xffu, wi, off);
                if (lane >= off) wi += n;
            }
            wsum[lane] = wi - wv;
            if (lane == 7) s_tot = wi;
        }
        __syncthreads();

        int pref = wsum[wid] + (incl - ts);  // exclusive prefix for this thread
#pragma unroll
        for (int j = 0; j < 16; j++) {
            int start = pref & 0xFFFF;
            int rank = pref >> 16;
            int c = cnts[j];
            if (c > 0) g_slotSC[b * KK + rank] = make_int2(start, c);
            g_off[b * KK + base + j] = start;  // scatter cursor (by voxel id)
            g_hist[b * KK + base + j] = 0;     // restore zero-invariant
            pref += e[j];
        }
        if (tid == 0) g_count[b] = (s_tot >> 16);
    }

    grid_sync(1);

    // ---- Phase 3: counting-sort scatter from register-held ids ----
#pragma unroll
    for (int j = 0; j < 4; j++) {
        int pos = atomicAdd(&g_off[b * KK + vid[j]], 1);
        g_sorted[b * NN + pos] = pid[j];
    }

    // batch_offset tail = cumsum(counts) (g_count complete since sync 1)
    if (out_tail != nullptr && blockIdx.x == 0 && b == 0 && tid == 0) {
        int acc = 0;
#pragma unroll
        for (int i = 0; i < BB; i++) {
            acc += g_count[i];
            out_tail[i] = (float)acc;
        }
    }
}

// Pool: one block per TWO output rows. 256 threads x float4 = one 4KB row.
// Per-warp coalesced index load + shuffle broadcast -> all cnt feature loads
// independent; streaming loads/stores (zero reuse anywhere).
__global__ __launch_bounds__(256) void pool_kernel(const float* __restrict__ feat,
                                                   float* __restrict__ out) {
    const int b = blockIdx.y;
    const int t = threadIdx.x;
    const int lane = t & 31;
    const float4* fb = reinterpret_cast<const float4*>(feat) + (size_t)b * NN * (FF / 4);

    const int slot0 = b * KK + blockIdx.x * 2;
    const int2 sc0 = g_slotSC[slot0];
    const int2 sc1 = g_slotSC[slot0 + 1];

#pragma unroll
    for (int s = 0; s < 2; s++) {
        const int slot = slot0 + s;
        const int2 sc = (s == 0) ? sc0 : sc1;
        float4* o = reinterpret_cast<float4*>(out) + (size_t)slot * (FF / 4);
        const int cnt = sc.y;
        if (cnt == 0) {
            __stcs(&o[t], make_float4(0.f, 0.f, 0.f, 0.f));
            continue;
        }

        const int* sp = g_sorted + b * NN + sc.x;
        float4 acc = make_float4(0.f, 0.f, 0.f, 0.f);
        for (int base = 0; base < cnt; base += 32) {
            int m = min(32, cnt - base);
            int myidx = (lane < m) ? sp[base + lane] : 0;
#pragma unroll 4
            for (int j = 0; j < m; j++) {
                int idx = __shfl_sync(0xffffffffu, myidx, j);
                float4 v = __ldcs(&fb[(size_t)idx * (FF / 4) + t]);
                acc.x += v.x; acc.y += v.y; acc.z += v.z; acc.w += v.w;
            }
        }

        float inv = 1.0f / (float)cnt;
        __stcs(&o[t], make_float4(acc.x * inv, acc.y * inv, acc.z * inv, acc.w * inv));
    }
}

extern "C" void kernel_launch(void* const* d_in, const int* in_sizes, int n_in,
                              void* d_out, int out_size) {
    const float* features = (const float*)d_in[0];
    const float* xyz = (const float*)d_in[1];
    if (n_in >= 2 && in_sizes[0] < in_sizes[1]) {
        features = (const float*)d_in[1];
        xyz = (const float*)d_in[0];
    }
    float* out = (float*)d_out;
    float* tail = (out_size > BB * KK * FF) ? out + (size_t)BB * KK * FF : nullptr;

    dim3 gbuild(9, BB);
    build_kernel<<<gbuild, 256>>>(xyz, tail);
    dim3 gpool(KK / 2, BB);
    pool_kernel<<<gpool, 256>>>(features, out);
}

// round 5
// speedup vs baseline: 1.0710x; 1.0710x over previous
#include <cuda_runtime.h>

#define BB 8
#define NN 9216
#define FF 1024
#define KK 4096

// Scratch (device globals; zero at module load; every call restores invariants)
__device__ int  g_hist[BB * KK];    // per-batch voxel histogram (zero on entry)
__device__ int  g_off[BB * KK];     // scatter cursor per voxel
__device__ int2 g_slotSC[BB * KK];  // per output slot (rank): {start, count}
__device__ int  g_vox[BB * NN];     // cached voxel id per point
__device__ int  g_sorted[BB * NN];  // point indices grouped by voxel
__device__ int  g_count[BB];        // occupied voxels per batch

// Compact voxel id: cx*256+cy*16+cz preserves the reference HASH_M=1024
// lexicographic ordering; the per-batch min subtraction is a constant per-axis
// shift and changes neither grouping nor order, hence ranks are unchanged.
__device__ __forceinline__ int voxel_id(const float* __restrict__ bx, int i) {
    float x = bx[i * 3 + 0];
    float y = bx[i * 3 + 1];
    float z = bx[i * 3 + 2];
    int cx = (int)floorf(__fdiv_rn(x, 0.2f));
    int cy = (int)floorf(__fdiv_rn(y, 0.2f));
    int cz = (int)floorf(__fdiv_rn(z, 0.2f));
    cx = min(max(cx, 0), 15);
    cy = min(max(cy, 0), 15);
    cz = min(max(cz, 0), 15);
    return (cx << 8) | (cy << 4) | cz;
}

// 1) voxelize + global histogram + cache ids. grid (9, BB) x 256, 4 pts/thread.
__global__ __launch_bounds__(256) void voxhist_kernel(const float* __restrict__ xyz) {
    const int b = blockIdx.y;
    const float* bx = xyz + (size_t)b * NN * 3;
#pragma unroll
    for (int j = 0; j < 4; j++) {
        int i = blockIdx.x * 1024 + threadIdx.x + j * 256;  // 9*1024 == NN
        int v = voxel_id(bx, i);
        g_vox[b * NN + i] = v;
        atomicAdd(&g_hist[b * KK + v], 1);
    }
}

// 2) per-batch packed dual exclusive scan over 4096 bins (4 bins/thread).
//    low 16 bits: point-count prefix (<=9216<2^16); high bits: occupancy
//    prefix == compacted rank. Writes slot table + scatter cursors + count,
//    re-zeroes g_hist to keep the cross-launch invariant.
__global__ __launch_bounds__(1024) void scan_kernel() {
    __shared__ int wsum[32];
    __shared__ int s_tot;

    const int b = blockIdx.x;
    const int tid = threadIdx.x;

    // zero the slot table (empty ranks must yield zero output rows)
    {
        int2 z = make_int2(0, 0);
#pragma unroll
        for (int j = 0; j < 4; j++) g_slotSC[b * KK + tid * 4 + j] = z;
    }

    const int base = tid * 4;
    int x0 = g_hist[b * KK + base + 0];
    int x1 = g_hist[b * KK + base + 1];
    int x2 = g_hist[b * KK + base + 2];
    int x3 = g_hist[b * KK + base + 3];
    int e0 = x0 | ((x0 > 0) << 16);
    int e1 = x1 | ((x1 > 0) << 16);
    int e2 = x2 | ((x2 > 0) << 16);
    int e3 = x3 | ((x3 > 0) << 16);
    int ts = e0 + e1 + e2 + e3;

    const int lane = tid & 31;
    const int wid = tid >> 5;

    int incl = ts;
#pragma unroll
    for (int off = 1; off < 32; off <<= 1) {
        int n = __shfl_up_sync(0xffffffffu, incl, off);
        if (lane >= off) incl += n;
    }
    if (lane == 31) wsum[wid] = incl;
    __syncthreads();

    if (wid == 0) {
        int wv = wsum[lane];
        int wi = wv;
#pragma unroll
        for (int off = 1; off < 32; off <<= 1) {
            int n = __shfl_up_sync(0xffffffffu, wi, off);
            if (lane >= off) wi += n;
        }
        wsum[lane] = wi - wv;
        if (lane == 31) s_tot = wi;
    }
    __syncthreads();

    int pref = wsum[wid] + (incl - ts);
    int es[4] = {e0, e1, e2, e3};
    int cs[4] = {x0, x1, x2, x3};
#pragma unroll
    for (int j = 0; j < 4; j++) {
        int start = pref & 0xFFFF;
        int rank = pref >> 16;
        if (cs[j] > 0) g_slotSC[b * KK + rank] = make_int2(start, cs[j]);
        g_off[b * KK + base + j] = start;  // scatter cursor (by voxel id)
        g_hist[b * KK + base + j] = 0;     // restore zero-invariant
        pref += es[j];
    }
    if (tid == 0) g_count[b] = (s_tot >> 16);
}

// 3) counting-sort scatter using cached ids. grid (9, BB) x 256, 4 pts/thread.
__global__ __launch_bounds__(256) void scatter_kernel() {
    const int b = blockIdx.y;
    const int i0 = blockIdx.x * 1024 + threadIdx.x;
#pragma unroll
    for (int j = 0; j < 4; j++) {
        int i = i0 + j * 256;
        int v = g_vox[b * NN + i];
        int pos = atomicAdd(&g_off[b * KK + v], 1);
        g_sorted[b * NN + pos] = i;
    }
}

// 4) pool: one block per FOUR output rows. 256 threads x float4 = one 4KB row.
//    All 4 descriptors and all 4 index-words prefetched before any gather so
//    the idx->feature dependent chains overlap across slots. Streaming ld/st.
//    Block (0,0) also writes the batch_offset tail.
__global__ __launch_bounds__(256) void pool_kernel(const float* __restrict__ feat,
                                                   float* __restrict__ out,
                                                   float* __restrict__ out_tail) {
    const int b = blockIdx.y;
    const int t = threadIdx.x;
    const int lane = t & 31;
    const float4* fb = reinterpret_cast<const float4*>(feat) + (size_t)b * NN * (FF / 4);
    const int* sbase = g_sorted + b * NN;

    if (out_tail != nullptr && blockIdx.x == 0 && b == 0 && t == 0) {
        int acc = 0;
#pragma unroll
        for (int i = 0; i < BB; i++) {
            acc += g_count[i];
            out_tail[i] = (float)acc;
        }
    }

    const int slot0 = b * KK + blockIdx.x * 4;

    // prefetch descriptors
    int2 sc[4];
#pragma unroll
    for (int s = 0; s < 4; s++) sc[s] = g_slotSC[slot0 + s];

    // prefetch first index word per slot (covers cnt<=32, i.e. ~always)
    int idx0[4];
#pragma unroll
    for (int s = 0; s < 4; s++)
        idx0[s] = (lane < sc[s].y) ? sbase[sc[s].x + lane] : 0;

#pragma unroll
    for (int s = 0; s < 4; s++) {
        const int cnt = sc[s].y;
        float4* o = reinterpret_cast<float4*>(out) + (size_t)(slot0 + s) * (FF / 4);
        if (cnt == 0) {
            __stcs(&o[t], make_float4(0.f, 0.f, 0.f, 0.f));
            continue;
        }

        float4 acc = make_float4(0.f, 0.f, 0.f, 0.f);
        int m0 = min(32, cnt);
#pragma unroll 4
        for (int j = 0; j < m0; j++) {
            int idx = __shfl_sync(0xffffffffu, idx0[s], j);
            float4 v = __ldcs(&fb[(size_t)idx * (FF / 4) + t]);
            acc.x += v.x; acc.y += v.y; acc.z += v.z; acc.w += v.w;
        }
        // rare spill: cnt > 32
        for (int base = 32; base < cnt; base += 32) {
            int m = min(32, cnt - base);
            int myidx = (lane < m) ? sbase[sc[s].x + base + lane] : 0;
            for (int j = 0; j < m; j++) {
                int idx = __shfl_sync(0xffffffffu, myidx, j);
                float4 v = __ldcs(&fb[(size_t)idx * (FF / 4) + t]);
                acc.x += v.x; acc.y += v.y; acc.z += v.z; acc.w += v.w;
            }
        }

        float inv = 1.0f / (float)cnt;
        __stcs(&o[t], make_float4(acc.x * inv, acc.y * inv, acc.z * inv, acc.w * inv));
    }
}

extern "C" void kernel_launch(void* const* d_in, const int* in_sizes, int n_in,
                              void* d_out, int out_size) {
    const float* features = (const float*)d_in[0];
    const float* xyz = (const float*)d_in[1];
    if (n_in >= 2 && in_sizes[0] < in_sizes[1]) {
        features = (const float*)d_in[1];
        xyz = (const float*)d_in[0];
    }
    float* out = (float*)d_out;
    float* tail = (out_size > BB * KK * FF) ? out + (size_t)BB * KK * FF : nullptr;

    dim3 gvox(9, BB);
    voxhist_kernel<<<gvox, 256>>>(xyz);
    scan_kernel<<<BB, 1024>>>();
    scatter_kernel<<<gvox, 256>>>();
    dim3 gpool(KK / 4, BB);
    pool_kernel<<<gpool, 256>>>(features, out, tail);
}